// round 5
// baseline (speedup 1.0000x reference)
#include <cuda_runtime.h>

// Problem constants (from reference):
//   B=16, H=128, W=128, C=256, P=8192
//   in_tensor: (B,H,W,C) float32, row-major
//   indices:   (B,P,2)   float32  (dim0 -> H, dim1 -> W)
//   out:       (B,P,C)   float32
//
// Bilinear gather: out = p1*(1-mx)(1-my) + p2*mx*(1-my) + p3*(1-mx)*my + p4*mx*my
//   p1 = in[b, floor(h), floor(w)]
//   p2 = in[b, ceil(h),  floor(w)]
//   p3 = in[b, floor(h), ceil(w)]
//   p4 = in[b, ceil(h),  ceil(w)]

#define GB (16)
#define GH (128)
#define GW (128)
#define GC (256)
#define GP (8192)

// 64 threads per point; each thread handles one float4 (4 channels).
// Block = 256 threads = 4 points.
__global__ __launch_bounds__(256) void grid_sample_kernel(
    const float* __restrict__ in_tensor,
    const float* __restrict__ indices,
    float* __restrict__ out)
{
    const int gid   = blockIdx.x * 256 + threadIdx.x;
    const int point = gid >> 6;        // global point id: 0 .. B*P-1
    const int lane  = gid & 63;        // float4 slot within the C=256 row

    // point -> b (p folded into flat addressing below)
    const int b = point >> 13;         // / 8192

    // Load the index pair for this point (broadcast across the 64 lanes; L1 hit)
    const float2 ind = __ldg(((const float2*)indices) + point);

    const float fx = floorf(ind.x);
    const float fy = floorf(ind.y);
    const float cx = ceilf(ind.x);
    const float cy = ceilf(ind.y);

    const int ifx = (int)fx;   // H index (floor)
    const int ify = (int)fy;   // W index (floor)
    const int icx = (int)cx;   // H index (ceil)
    const int icy = (int)cy;   // W index (ceil)

    const float mx = ind.x - fx;
    const float my = ind.y - fy;
    const float omx = 1.0f - mx;
    const float omy = 1.0f - my;

    const float w1 = omx * omy;
    const float w2 = mx  * omy;
    const float w3 = omx * my;
    const float w4 = mx  * my;

    // Base of this batch image, in float4 units (C=256 floats = 64 float4 per (h,w) cell)
    const float4* base = ((const float4*)in_tensor) + (size_t)b * (GH * GW * (GC / 4));

    const float4* r1 = base + (size_t)(ifx * GW + ify) * (GC / 4) + lane;
    const float4* r2 = base + (size_t)(icx * GW + ify) * (GC / 4) + lane;
    const float4* r3 = base + (size_t)(ifx * GW + icy) * (GC / 4) + lane;
    const float4* r4 = base + (size_t)(icx * GW + icy) * (GC / 4) + lane;

    // 4 independent 16B loads -> MLP=4 per thread
    const float4 v1 = __ldg(r1);
    const float4 v2 = __ldg(r2);
    const float4 v3 = __ldg(r3);
    const float4 v4 = __ldg(r4);

    float4 o;
    o.x = v1.x * w1 + v2.x * w2 + v3.x * w3 + v4.x * w4;
    o.y = v1.y * w1 + v2.y * w2 + v3.y * w3 + v4.y * w4;
    o.z = v1.z * w1 + v2.z * w2 + v3.z * w3 + v4.z * w4;
    o.w = v1.w * w1 + v2.w * w2 + v3.w * w3 + v4.w * w4;

    // Output is write-once, never re-read by this kernel: streaming store
    // (evict-first) keeps L2 capacity for the gather traffic, which has reuse.
    __stcs(((float4*)out) + (size_t)point * (GC / 4) + lane, o);
}

extern "C" void kernel_launch(void* const* d_in, const int* in_sizes, int n_in,
                              void* d_out, int out_size)
{
    const float* in_tensor = (const float*)d_in[0];  // (B,H,W,C) f32
    const float* indices   = (const float*)d_in[1];  // (B,P,2)  f32
    float*       out       = (float*)d_out;          // (B,P,C)  f32

    // Total threads = B*P*64 = 8,388,608 -> 32768 blocks of 256
    const int total_points = GB * GP;
    const int blocks = (total_points * 64) / 256;
    grid_sample_kernel<<<blocks, 256>>>(in_tensor, indices, out);
}

// round 6
// speedup vs baseline: 1.0894x; 1.0894x over previous
#include <cuda_runtime.h>

// Problem constants (from reference):
//   B=16, H=128, W=128, C=256, P=8192
//   in_tensor: (B,H,W,C) float32, row-major
//   indices:   (B,P,2)   float32  (dim0 -> H, dim1 -> W)
//   out:       (B,P,C)   float32
//
// Bilinear gather: out = p1*(1-mx)(1-my) + p2*mx*(1-my) + p3*(1-mx)*my + p4*mx*my
//   p1 = in[b, floor(h), floor(w)]
//   p2 = in[b, ceil(h),  floor(w)]
//   p3 = in[b, floor(h), ceil(w)]
//   p4 = in[b, ceil(h),  ceil(w)]
//
// Round-5 finding: DRAM only 58.8% busy with nothing else saturated -> latency
// bound, MLP too low (4 loads/thread). This version: 32 threads/point, each
// thread owns 2 float4 slots per corner row -> 8 independent LDG.128 in
// flight per thread (MLP=8), same coalesced access pattern.

#define GB (16)
#define GH (128)
#define GW (128)
#define GC (256)
#define GP (8192)

__global__ __launch_bounds__(256) void grid_sample_kernel(
    const float* __restrict__ in_tensor,
    const float* __restrict__ indices,
    float* __restrict__ out)
{
    const int gid   = blockIdx.x * 256 + threadIdx.x;
    const int point = gid >> 5;        // global point id: 0 .. B*P-1
    const int lane  = gid & 31;        // first float4 slot (second is lane+32)

    const int b = point >> 13;         // / P(=8192)

    // Index pair for this point (broadcast across the 32 lanes)
    const float2 ind = __ldg(((const float2*)indices) + point);

    const float fx = floorf(ind.x);
    const float fy = floorf(ind.y);
    const float cx = ceilf(ind.x);
    const float cy = ceilf(ind.y);

    const int ifx = (int)fx;   // H floor
    const int ify = (int)fy;   // W floor
    const int icx = (int)cx;   // H ceil
    const int icy = (int)cy;   // W ceil

    const float mx = ind.x - fx;
    const float my = ind.y - fy;
    const float omx = 1.0f - mx;
    const float omy = 1.0f - my;

    const float w1 = omx * omy;
    const float w2 = mx  * omy;
    const float w3 = omx * my;
    const float w4 = mx  * my;

    // Base of this batch image in float4 units (C=256 floats = 64 float4/cell)
    const float4* base = ((const float4*)in_tensor) + (size_t)b * (GH * GW * (GC / 4));

    const float4* r1 = base + (size_t)(ifx * GW + ify) * (GC / 4) + lane;
    const float4* r2 = base + (size_t)(icx * GW + ify) * (GC / 4) + lane;
    const float4* r3 = base + (size_t)(ifx * GW + icy) * (GC / 4) + lane;
    const float4* r4 = base + (size_t)(icx * GW + icy) * (GC / 4) + lane;

    // 8 independent 16B loads -> MLP=8 per thread
    const float4 v1a = __ldg(r1);
    const float4 v2a = __ldg(r2);
    const float4 v3a = __ldg(r3);
    const float4 v4a = __ldg(r4);
    const float4 v1b = __ldg(r1 + 32);
    const float4 v2b = __ldg(r2 + 32);
    const float4 v3b = __ldg(r3 + 32);
    const float4 v4b = __ldg(r4 + 32);

    float4 oa, ob;
    oa.x = v1a.x * w1 + v2a.x * w2 + v3a.x * w3 + v4a.x * w4;
    oa.y = v1a.y * w1 + v2a.y * w2 + v3a.y * w3 + v4a.y * w4;
    oa.z = v1a.z * w1 + v2a.z * w2 + v3a.z * w3 + v4a.z * w4;
    oa.w = v1a.w * w1 + v2a.w * w2 + v3a.w * w3 + v4a.w * w4;

    ob.x = v1b.x * w1 + v2b.x * w2 + v3b.x * w3 + v4b.x * w4;
    ob.y = v1b.y * w1 + v2b.y * w2 + v3b.y * w3 + v4b.y * w4;
    ob.z = v1b.z * w1 + v2b.z * w2 + v3b.z * w3 + v4b.z * w4;
    ob.w = v1b.w * w1 + v2b.w * w2 + v3b.w * w3 + v4b.w * w4;

    // Write-once output: streaming store keeps L2 for gather reuse.
    float4* o = ((float4*)out) + (size_t)point * (GC / 4) + lane;
    __stcs(o,      oa);
    __stcs(o + 32, ob);
}

extern "C" void kernel_launch(void* const* d_in, const int* in_sizes, int n_in,
                              void* d_out, int out_size)
{
    const float* in_tensor = (const float*)d_in[0];  // (B,H,W,C) f32
    const float* indices   = (const float*)d_in[1];  // (B,P,2)  f32
    float*       out       = (float*)d_out;          // (B,P,C)  f32

    // Total threads = B*P*32 = 4,194,304 -> 16384 blocks of 256
    const int total_points = GB * GP;
    const int blocks = (total_points * 32) / 256;
    grid_sample_kernel<<<blocks, 256>>>(in_tensor, indices, out);
}